// round 2
// baseline (speedup 1.0000x reference)
#include <cuda_runtime.h>
#include <math.h>

#define NROWS 1024
#define C 64
#define MARGIN_F 15.0f
#define EPSJ 1e-8f
#define BT 64
#define PAD 65

// ---------------- scratch (static device globals; no allocation) ----------------
__device__ float g_Sa[2][NROWS];     // per-row sum A*logA (A = x_prob + eps)
__device__ float g_nn[2][NROWS];     // per-row ||x||^2
__device__ float g_rowsum[NROWS];    // negative-branch per-row pair sums
__device__ int   g_rowcnt[NROWS];    // negative-branch per-row counts (pairs > 0)
__device__ float g_acc[2];           // [0] = posi sum (both branches), [1] = ood sum

// ---------------- fast log: poly on FMA pipe (avoids MUFU bottleneck) -----------
// x in [5e-9, ~1]. Taylor deg-10 about 1 after sqrt(2) reduction; |err| < ~6e-6.
__device__ __forceinline__ float flog(float x) {
    int ix = __float_as_int(x);
    float ef = (float)((ix >> 23) - 127);
    float f  = __int_as_float((ix & 0x007FFFFF) | 0x3F800000);   // [1,2)
    if (f > 1.41421356f) { f *= 0.5f; ef += 1.0f; }
    float t = f - 1.0f;                                          // [-0.293, 0.414]
    float p = -0.1f;
    p = fmaf(p, t,  0.111111111f);
    p = fmaf(p, t, -0.125f);
    p = fmaf(p, t,  0.142857143f);
    p = fmaf(p, t, -0.166666667f);
    p = fmaf(p, t,  0.2f);
    p = fmaf(p, t, -0.25f);
    p = fmaf(p, t,  0.333333333f);
    p = fmaf(p, t, -0.5f);
    p = fmaf(p, t,  1.0f);
    p *= t;
    return fmaf(ef, 0.693147181f, p);
}

// ---------------- kernel 0: zero scratch ----------------------------------------
__global__ void zero_kernel() {
    int t = blockIdx.x * blockDim.x + threadIdx.x;
    if (t < NROWS) { g_rowsum[t] = 0.0f; g_rowcnt[t] = 0; }
    if (t < 2) g_acc[t] = 0.0f;
}

// ---------------- kernel 1: per-row precompute + positive + ood branches --------
// one thread per row, 2048 rows (branch 0: x1 set; branch 1: x2 set).
// Closed forms exploiting one-hot structure:
//   kl_am[i,j] = P[i] + A_ij*(L0_ij - L1_ij)
//   kl_bm[i,j] = eps*((C-1)*log(eps) - (T[i] - L0_ij)) - L1_ij      (1+eps == 1.0f in fp32)
// with L0 = log(0.5*(A+eps)), L1 = log(0.5*(A+1)).
// pos_dist[i,j] == ood d[i,j] == sqrt(max(||x_i||^2 - 2 x_ij + 1, 1e-12)).
__global__ void row_kernel(const float* __restrict__ x1, const float* __restrict__ x2,
                           const float* __restrict__ xp1, const float* __restrict__ xp2,
                           const float* __restrict__ l1,  const float* __restrict__ l2) {
    int gid = blockIdx.x * blockDim.x + threadIdx.x;
    if (gid >= 2 * NROWS) return;
    int br = gid >> 10;
    int i  = gid & (NROWS - 1);
    const float* xr = (br ? x2  : x1)  + i * C;
    const float* pr = (br ? xp2 : xp1) + i * C;
    const float* lr = (br ? l2  : l1)  + i * C;

    float P = 0.0f, T = 0.0f, Sa = 0.0f, nn = 0.0f;
    #pragma unroll 4
    for (int c = 0; c < C; c++) {
        float A  = pr[c] + EPSJ;
        float la = __logf(A);
        float L0 = __logf(0.5f * (A + EPSJ));
        P  += A * (la - L0);
        T  += L0;
        Sa += A * la;
        float xv = xr[c];
        nn += xv * xv;
    }
    g_Sa[br][i] = Sa;
    g_nn[br][i] = nn;

    const float LOGEPS = -18.42068074f;   // ln(1e-8)
    float posi = 0.0f, var = 0.0f, mn = 1e30f;
    #pragma unroll 4
    for (int j = 0; j < C; j++) {
        float A  = pr[j] + EPSJ;
        float L0 = __logf(0.5f * (A + EPSJ));
        float L1 = __logf(0.5f * (A + 1.0f));
        float kl_am = P + A * (L0 - L1);
        float kl_bm = EPSJ * ((float)(C - 1) * LOGEPS - (T - L0)) - L1;
        float js = 1.0f - 0.5f * kl_am - 0.5f * kl_bm;
        float d2 = fmaxf(nn - 2.0f * xr[j] + 1.0f, 1e-12f);
        float pd = sqrtf(d2);
        posi += pd * lr[j] * js;
        float od = fmaxf(MARGIN_F - pd, 0.0f);
        float r  = od * (1.0f / MARGIN_F);
        var += r * r;
        mn = fminf(mn, 1.0f - r);
    }
    atomicAdd(&g_acc[0], posi);
    atomicAdd(&g_acc[1], var * mn);
}

// ---------------- kernel 2: pairwise negative branch ----------------------------
// 64x64 tile per block, 16x16 threads, 4x4 register tile (strided i = ty+16k,
// j = tx+16k). Smem stored [c][row] with PAD=65 -> all LDS conflict-free.
// js[i,j] = 0.5*(Sa1[i]+Sa2[j]) - sum_c M*log(M), M = (A1_ic + A2_jc)/2.
__global__ void __launch_bounds__(256, 2)
pair_kernel(const float* __restrict__ x1, const float* __restrict__ x2,
            const float* __restrict__ xp1, const float* __restrict__ xp2,
            const float* __restrict__ l1,  const float* __restrict__ l2) {
    extern __shared__ float sm[];
    float* sA  = sm;                 // x_prob1 + eps, [C][PAD]
    float* sLi = sA  + C * PAD;
    float* sXi = sLi + C * PAD;
    float* sB  = sXi + C * PAD;      // x_prob2 + eps
    float* sLj = sB  + C * PAD;
    float* sXj = sLj + C * PAD;

    const int tx = threadIdx.x, ty = threadIdx.y;
    const int tid = ty * 16 + tx;
    const int i0 = blockIdx.y * BT, j0 = blockIdx.x * BT;

    for (int idx = tid; idx < BT * C; idx += 256) {
        int c = idx & (C - 1);
        int r = idx >> 6;
        sA [c * PAD + r] = xp1[(i0 + r) * C + c] + EPSJ;
        sLi[c * PAD + r] = l1 [(i0 + r) * C + c];
        sXi[c * PAD + r] = x1 [(i0 + r) * C + c];
        sB [c * PAD + r] = xp2[(j0 + r) * C + c] + EPSJ;
        sLj[c * PAD + r] = l2 [(j0 + r) * C + c];
        sXj[c * PAD + r] = x2 [(j0 + r) * C + c];
    }
    __syncthreads();

    float jsum[4][4], dl[4][4], dx[4][4];
    #pragma unroll
    for (int a = 0; a < 4; a++)
        #pragma unroll
        for (int b = 0; b < 4; b++) { jsum[a][b] = 0.0f; dl[a][b] = 0.0f; dx[a][b] = 0.0f; }

    #pragma unroll 2
    for (int c = 0; c < C; c++) {
        float a[4], li[4], xi[4], b[4], lj[4], xj[4];
        #pragma unroll
        for (int k = 0; k < 4; k++) {
            a [k] = sA [c * PAD + ty + 16 * k];
            li[k] = sLi[c * PAD + ty + 16 * k];
            xi[k] = sXi[c * PAD + ty + 16 * k];
            b [k] = sB [c * PAD + tx + 16 * k];
            lj[k] = sLj[c * PAD + tx + 16 * k];
            xj[k] = sXj[c * PAD + tx + 16 * k];
        }
        #pragma unroll
        for (int ki = 0; ki < 4; ki++)
            #pragma unroll
            for (int kj = 0; kj < 4; kj++) {
                float m = 0.5f * (a[ki] + b[kj]);
                jsum[ki][kj] = fmaf(m, flog(m), jsum[ki][kj]);
                dl  [ki][kj] = fmaf(li[ki], lj[kj], dl[ki][kj]);
                dx  [ki][kj] = fmaf(xi[ki], xj[kj], dx[ki][kj]);
            }
    }

    float Sb[4], nb[4];
    #pragma unroll
    for (int kj = 0; kj < 4; kj++) {
        int j = j0 + tx + 16 * kj;
        Sb[kj] = g_Sa[1][j];
        nb[kj] = g_nn[1][j];
    }

    #pragma unroll
    for (int ki = 0; ki < 4; ki++) {
        int i = i0 + ty + 16 * ki;
        float Sai = g_Sa[0][i];
        float nai = g_nn[0][i];
        float rsum = 0.0f;
        int   rcnt = 0;
        #pragma unroll
        for (int kj = 0; kj < 4; kj++) {
            float js = 0.5f * (Sai + Sb[kj]) - jsum[ki][kj];
            float d2 = fmaxf(nai + nb[kj] - 2.0f * dx[ki][kj], 1e-12f);
            float ed = sqrtf(d2) + 1e-10f;
            float hinge = fmaxf(MARGIN_F - ed, 0.0f);
            float pr = hinge * (1.0f - dl[ki][kj]) * js;
            rsum += pr;
            rcnt += (pr > 0.0f) ? 1 : 0;
        }
        // reduce over the 16 tx lanes (width-16 groups within the warp)
        #pragma unroll
        for (int off = 8; off; off >>= 1) {
            rsum += __shfl_down_sync(0xffffffffu, rsum, off, 16);
            rcnt += __shfl_down_sync(0xffffffffu, rcnt, off, 16);
        }
        if (tx == 0) {
            atomicAdd(&g_rowsum[i], rsum);
            atomicAdd(&g_rowcnt[i], rcnt);
        }
    }
}

// ---------------- kernel 3: finalize --------------------------------------------
__global__ void final_kernel(float* __restrict__ out, int out_size) {
    __shared__ float red[256];
    int t = threadIdx.x;
    float s = 0.0f;
    for (int i = t; i < NROWS; i += 256) {
        int c = g_rowcnt[i];
        float cf = (c == 0) ? 1.0f : (float)c;
        s += g_rowsum[i] / cf;
    }
    red[t] = s;
    __syncthreads();
    for (int off = 128; off; off >>= 1) {
        if (t < off) red[t] += red[t + off];
        __syncthreads();
    }
    // defensive: clear any extra output slots (buffer is poisoned 0xAA)
    for (int i = t; i < out_size; i += 256) out[i] = 0.0f;
    __syncthreads();
    if (t == 0) {
        float nega = red[0];
        float posi = 0.5f * g_acc[0];
        float oodt = 0.5f * g_acc[1];
        float loss = posi + nega + 0.5f * oodt;   // LAM = 0.5
        if (out_size > 0) out[0] = loss;
        if (out_size > 1) out[1] = posi;
        if (out_size > 2) out[2] = nega;
    }
}

// ---------------- launch ---------------------------------------------------------
extern "C" void kernel_launch(void* const* d_in, const int* in_sizes, int n_in,
                              void* d_out, int out_size) {
    const float* x1  = (const float*)d_in[0];
    const float* x2  = (const float*)d_in[1];
    const float* xp1 = (const float*)d_in[2];
    const float* xp2 = (const float*)d_in[3];
    const float* l1  = (const float*)d_in[4];
    const float* l2  = (const float*)d_in[5];
    float* out = (float*)d_out;

    zero_kernel<<<4, 256>>>();
    row_kernel<<<32, 64>>>(x1, x2, xp1, xp2, l1, l2);

    const int smem_bytes = 6 * C * PAD * (int)sizeof(float);   // 99,840 B
    cudaFuncSetAttribute(pair_kernel, cudaFuncAttributeMaxDynamicSharedMemorySize,
                         smem_bytes);
    pair_kernel<<<dim3(16, 16), dim3(16, 16), smem_bytes>>>(x1, x2, xp1, xp2, l1, l2);

    final_kernel<<<1, 256>>>(out, out_size);
}

// round 3
// speedup vs baseline: 1.6042x; 1.6042x over previous
#include <cuda_runtime.h>
#include <math.h>

#define NROWS 1024
#define C 64
#define MARGIN_F 15.0f
#define EPSJ 1e-8f
#define HLN2 0.34657359027997264f   /* 0.5*ln2 */
#define BT 64
#define SPAD 65

// ---------------- scratch (static device globals; no allocation) ----------------
__device__ float g_K[2][NROWS];      // 0.5*Sa + 0.5*ln2*sumA  per row
__device__ float g_nn[2][NROWS];     // ||x||^2 per row
__device__ float g_pos[2 * NROWS];   // per-row positive-branch contribution
__device__ float g_oodv[2 * NROWS];  // per-row ood contribution (var*coffi)
__device__ float g_rowsum[NROWS];    // negative-branch per-row pair sums
__device__ int   g_rowcnt[NROWS];    // negative-branch per-row counts (pairs > 0)
__device__ int   g_done;             // pair-kernel completion counter

__device__ __forceinline__ unsigned long long fma2(unsigned long long a,
                                                   unsigned long long b,
                                                   unsigned long long c) {
    unsigned long long d;
    asm("fma.rn.f32x2 %0, %1, %2, %3;" : "=l"(d) : "l"(a), "l"(b), "l"(c));
    return d;
}

// ---------------- kernel 1: per-row precompute + positive + ood branches --------
// One thread per (branch,row). Single fused pass using one-hot closed forms:
//   js_j = G + h_j,  G = 1 - 0.5P - 0.5eps(C-1)ln(eps) + 0.5eps*T   (row const)
//   h_j  = -0.5A_j(L0_j - L1_j) - 0.5eps*L0_j + 0.5L1_j
//   posi_row = G*sum(pd*l) + sum(pd*l*h)
// pos_dist == ood cdist == sqrt(max(||x||^2 - 2x_j + 1, 1e-12)).
// Also zeroes pair-kernel scratch (runs strictly before pair_kernel on stream).
__global__ void row_kernel(const float* __restrict__ x1, const float* __restrict__ x2,
                           const float* __restrict__ xp1, const float* __restrict__ xp2,
                           const float* __restrict__ l1,  const float* __restrict__ l2) {
    int gid = blockIdx.x * blockDim.x + threadIdx.x;
    if (gid >= 2 * NROWS) return;
    if (gid == 0) g_done = 0;
    if (gid < NROWS) { g_rowsum[gid] = 0.0f; g_rowcnt[gid] = 0; }

    int br = gid >> 10;
    int i  = gid & (NROWS - 1);
    const float* xr = (br ? x2  : x1)  + i * C;
    const float* pr = (br ? xp2 : xp1) + i * C;
    const float* lr = (br ? l2  : l1)  + i * C;

    float nn = 0.0f, sumA = 0.0f;
    #pragma unroll 8
    for (int c = 0; c < C; c++) {
        float xv = xr[c];
        nn = fmaf(xv, xv, nn);
        sumA += pr[c] + EPSJ;
    }

    float P = 0.0f, T = 0.0f, Sa = 0.0f, S1 = 0.0f, S2 = 0.0f;
    float var = 0.0f, mn = 1e30f;
    #pragma unroll 4
    for (int c = 0; c < C; c++) {
        float A  = pr[c] + EPSJ;
        float la = __logf(A);
        float L0 = __logf(0.5f * (A + EPSJ));
        float L1 = __logf(0.5f * (A + 1.0f));
        P  += A * (la - L0);
        T  += L0;
        Sa += A * la;
        float pd = sqrtf(fmaxf(nn - 2.0f * xr[c] + 1.0f, 1e-12f));
        float h  = -0.5f * A * (L0 - L1) - 0.5f * EPSJ * L0 + 0.5f * L1;
        float w  = pd * lr[c];
        S1 += w;
        S2 += w * h;
        float r = fmaxf(MARGIN_F - pd, 0.0f) * (1.0f / MARGIN_F);
        var = fmaf(r, r, var);
        mn  = fminf(mn, 1.0f - r);
    }
    const float LOGEPS = -18.420680743952367f;   // ln(1e-8)
    float G = 1.0f - 0.5f * P - 0.5f * EPSJ * (float)(C - 1) * LOGEPS + 0.5f * EPSJ * T;

    g_pos [gid]   = G * S1 + S2;
    g_oodv[gid]   = var * mn;
    g_K [br][i]   = 0.5f * Sa + HLN2 * sumA;
    g_nn[br][i]   = nn;
}

// ---------------- kernel 2: pairwise negative branch + folded finalize ----------
// 64x64 tile per block, 16x16 threads, 4x4 register tile.
// js[i,j] = Ka[i] + Kb[j] - 0.5*ln2 * sum_c s*lg2(s),  s = A1_ic + A2_jc.
// (uses sum_c s = sumA_i + sumB_j folded into Ka/Kb, so inner loop is
//  FADD + MUFU.LG2 + FFMA per pair-c; dl/dx grams ride one packed f32x2 FMA.)
// Last finishing block performs the global reduction and writes the output.
__global__ void __launch_bounds__(256, 2)
pair_kernel(const float* __restrict__ x1, const float* __restrict__ x2,
            const float* __restrict__ xp1, const float* __restrict__ xp2,
            const float* __restrict__ l1,  const float* __restrict__ l2,
            float* __restrict__ out, int out_size) {
    extern __shared__ float sm[];
    float*  sA   = sm;                                   // [C][SPAD]  xp1+eps
    float*  sB   = sm + C * SPAD;                        // [C][SPAD]  xp2+eps
    float2* sPi  = (float2*)(sm + 2 * C * SPAD);         // [C][SPAD]  (l1, x1)
    float2* sPj  = sPi + C * SPAD;                       // [C][SPAD]  (l2, x2)
    const unsigned long long* sPi64 = (const unsigned long long*)sPi;
    const unsigned long long* sPj64 = (const unsigned long long*)sPj;

    const int tx = threadIdx.x, ty = threadIdx.y;
    const int tid = ty * 16 + tx;
    const int i0 = blockIdx.y * BT, j0 = blockIdx.x * BT;

    for (int idx = tid; idx < BT * C; idx += 256) {
        int c = idx & (C - 1);
        int r = idx >> 6;
        sA[c * SPAD + r] = xp1[(i0 + r) * C + c] + EPSJ;
        sB[c * SPAD + r] = xp2[(j0 + r) * C + c] + EPSJ;
        sPi[c * SPAD + r] = make_float2(l1[(i0 + r) * C + c], x1[(i0 + r) * C + c]);
        sPj[c * SPAD + r] = make_float2(l2[(j0 + r) * C + c], x2[(j0 + r) * C + c]);
    }
    __syncthreads();

    float jsum[4][4];
    unsigned long long dlx[4][4];
    #pragma unroll
    for (int a = 0; a < 4; a++)
        #pragma unroll
        for (int b = 0; b < 4; b++) { jsum[a][b] = 0.0f; dlx[a][b] = 0ull; }

    #pragma unroll 2
    for (int c = 0; c < C; c++) {
        float a[4], b[4];
        unsigned long long pi[4], pj[4];
        #pragma unroll
        for (int k = 0; k < 4; k++) {
            a [k] = sA[c * SPAD + ty + 16 * k];
            b [k] = sB[c * SPAD + tx + 16 * k];
            pi[k] = sPi64[c * SPAD + ty + 16 * k];
            pj[k] = sPj64[c * SPAD + tx + 16 * k];
        }
        #pragma unroll
        for (int ki = 0; ki < 4; ki++)
            #pragma unroll
            for (int kj = 0; kj < 4; kj++) {
                float s = a[ki] + b[kj];
                float u = __log2f(s);                       // MUFU.LG2
                jsum[ki][kj] = fmaf(s, u, jsum[ki][kj]);
                dlx[ki][kj]  = fma2(pi[ki], pj[kj], dlx[ki][kj]);
            }
    }

    float Kb[4], nb[4];
    #pragma unroll
    for (int kj = 0; kj < 4; kj++) {
        int j = j0 + tx + 16 * kj;
        Kb[kj] = g_K[1][j];
        nb[kj] = g_nn[1][j];
    }

    #pragma unroll
    for (int ki = 0; ki < 4; ki++) {
        int i = i0 + ty + 16 * ki;
        float Ka = g_K[0][i];
        float na = g_nn[0][i];
        float rsum = 0.0f;
        int   rcnt = 0;
        #pragma unroll
        for (int kj = 0; kj < 4; kj++) {
            float2 v = *(float2*)&dlx[ki][kj];              // (dl, dx)
            float js = Ka + Kb[kj] - HLN2 * jsum[ki][kj];
            float d2 = fmaxf(na + nb[kj] - 2.0f * v.y, 1e-12f);
            float ed = sqrtf(d2) + 1e-10f;
            float hinge = fmaxf(MARGIN_F - ed, 0.0f);
            float pr = hinge * (1.0f - v.x) * js;
            rsum += pr;
            rcnt += (pr > 0.0f) ? 1 : 0;
        }
        #pragma unroll
        for (int off = 8; off; off >>= 1) {
            rsum += __shfl_down_sync(0xffffffffu, rsum, off, 16);
            rcnt += __shfl_down_sync(0xffffffffu, rcnt, off, 16);
        }
        if (tx == 0) {
            atomicAdd(&g_rowsum[i], rsum);
            atomicAdd(&g_rowcnt[i], rcnt);
        }
    }

    // ---- folded finalize: last block to finish reduces everything ----
    __threadfence();
    __syncthreads();
    if (tid == 0) ((int*)sm)[0] = atomicAdd(&g_done, 1);
    __syncthreads();
    int last = (((int*)sm)[0] == 255);
    __syncthreads();
    if (!last) return;

    float nega = 0.0f, posi = 0.0f, ood = 0.0f;
    for (int r = tid; r < NROWS; r += 256) {
        float rs = __ldcg(&g_rowsum[r]);
        int   rc = __ldcg(&g_rowcnt[r]);
        nega += rs / (float)(rc > 0 ? rc : 1);
    }
    for (int r = tid; r < 2 * NROWS; r += 256) {
        posi += g_pos[r];
        ood  += g_oodv[r];
    }
    float* red = sm;            // reuse smem: 3 x 256 floats
    red[tid]       = nega;
    red[256 + tid] = posi;
    red[512 + tid] = ood;
    __syncthreads();
    for (int off = 128; off; off >>= 1) {
        if (tid < off) {
            red[tid]       += red[tid + off];
            red[256 + tid] += red[256 + tid + off];
            red[512 + tid] += red[512 + tid + off];
        }
        __syncthreads();
    }
    for (int r = 3 + tid; r < out_size; r += 256) out[r] = 0.0f;  // defensive
    if (tid == 0) {
        float ng = red[0];
        float ps = 0.5f * red[256];
        float od = 0.5f * red[512];
        if (out_size > 0) out[0] = ps + ng + 0.5f * od;   // LAM = 0.5
        if (out_size > 1) out[1] = ps;
        if (out_size > 2) out[2] = ng;
    }
}

// ---------------- launch ---------------------------------------------------------
extern "C" void kernel_launch(void* const* d_in, const int* in_sizes, int n_in,
                              void* d_out, int out_size) {
    const float* x1  = (const float*)d_in[0];
    const float* x2  = (const float*)d_in[1];
    const float* xp1 = (const float*)d_in[2];
    const float* xp2 = (const float*)d_in[3];
    const float* l1  = (const float*)d_in[4];
    const float* l2  = (const float*)d_in[5];
    float* out = (float*)d_out;

    row_kernel<<<16, 128>>>(x1, x2, xp1, xp2, l1, l2);

    const int smem_bytes = (2 * C * SPAD + 4 * C * SPAD) * (int)sizeof(float); // 99,840 B
    cudaFuncSetAttribute(pair_kernel, cudaFuncAttributeMaxDynamicSharedMemorySize,
                         smem_bytes);
    pair_kernel<<<dim3(16, 16), dim3(16, 16), smem_bytes>>>(x1, x2, xp1, xp2, l1, l2,
                                                            out, out_size);
}